// round 2
// baseline (speedup 1.0000x reference)
#include <cuda_runtime.h>
#include <cstdint>

#define BB     2
#define NN     8192
#define KK     10
#define TPB    128
#define TILE   1024
#define SEG    4
#define SEGLEN (NN / SEG)   // 2048

// Scratch (no device allocation allowed)
__device__ float4 g_pts[BB * NN];            // {x, y, z, |p|^2} of point1
__device__ float4 g_q[BB * NN];              // {p1-p2, 0}
__device__ float  g_top_d[SEG * BB * NN * KK];
__device__ int    g_top_i[SEG * BB * NN * KK];
__device__ float  g_acc;

__global__ void prep_kernel(const float* __restrict__ p1,
                            const float* __restrict__ p2) {
    int i = blockIdx.x * blockDim.x + threadIdx.x;
    if (i == 0) g_acc = 0.0f;
    if (i < BB * NN) {
        float x = p1[3 * i + 0], y = p1[3 * i + 1], z = p1[3 * i + 2];
        float a = p2[3 * i + 0], b = p2[3 * i + 1], c = p2[3 * i + 2];
        g_pts[i] = make_float4(x, y, z, x * x + y * y + z * z);
        g_q[i]   = make_float4(x - a, y - b, z - c, 0.0f);
    }
}

// grid: (NN/TPB, BB, SEG). One thread per query; scans SEGLEN candidates.
__global__ __launch_bounds__(TPB) void knn_seg_kernel() {
    __shared__ float4 tile[TILE];

    const int b   = blockIdx.y;
    const int s   = blockIdx.z;
    const int qi  = blockIdx.x * TPB + threadIdx.x;     // query index in batch
    const int c0  = s * SEGLEN;                          // candidate segment start
    const float4* __restrict__ pts = g_pts + b * NN;

    const float4 me = pts[qi];

    float dist[KK];
    int   nn[KK];
#pragma unroll
    for (int k = 0; k < KK; ++k) {
        dist[k] = __int_as_float(0x7f800000);  // +inf
        nn[k]   = -1;
    }

    for (int t = c0; t < c0 + SEGLEN; t += TILE) {
#pragma unroll
        for (int j = threadIdx.x; j < TILE; j += TPB)
            tile[j] = pts[t + j];
        __syncthreads();

#pragma unroll 16
        for (int j = 0; j < TILE; ++j) {
            float4 c  = tile[j];
            float dot = me.x * c.x + me.y * c.y + me.z * c.z;
            float d2  = (me.w + c.w) - 2.0f * dot;   // matches reference formula
            int   gj  = t + j;
            if (d2 < dist[KK - 1] && gj != qi) {
                dist[KK - 1] = d2;
                nn[KK - 1]   = gj;
#pragma unroll
                for (int k = KK - 1; k > 0; --k) {
                    if (dist[k] < dist[k - 1]) {
                        float td = dist[k]; dist[k] = dist[k - 1]; dist[k - 1] = td;
                        int   ti = nn[k];   nn[k]   = nn[k - 1];   nn[k - 1]   = ti;
                    } else {
                        break;
                    }
                }
            }
        }
        __syncthreads();
    }

    // write sorted partial top-10
    long base = (((long)s * BB + b) * NN + qi) * KK;
#pragma unroll
    for (int k = 0; k < KK; ++k) {
        g_top_d[base + k] = dist[k];
        g_top_i[base + k] = nn[k];
    }
}

// One thread per query: 4-way merge of sorted lists, then loss contribution.
__global__ __launch_bounds__(256) void merge_loss_kernel() {
    __shared__ float wsum[256 / 32];

    int q = blockIdx.x * blockDim.x + threadIdx.x;   // global query [0, BB*NN)
    int b  = q / NN;
    int qi = q - b * NN;

    // heads of the 4 sorted lists
    float hd[SEG];
    int   hi[SEG];
    int   p[SEG];
#pragma unroll
    for (int s = 0; s < SEG; ++s) {
        long base = (((long)s * BB + b) * NN + qi) * KK;
        hd[s] = g_top_d[base];
        hi[s] = g_top_i[base];
        p[s]  = 1;
    }

    const float4* __restrict__ qv = g_q + b * NN;
    float sx = 0.0f, sy = 0.0f, sz = 0.0f;

#pragma unroll
    for (int k = 0; k < KK; ++k) {
        // argmin over segment heads; ties -> lower segment (lower index) wins
        int   bs = 0;
        float bd = hd[0];
#pragma unroll
        for (int s = 1; s < SEG; ++s) {
            if (hd[s] < bd) { bd = hd[s]; bs = s; }
        }
        float4 v = __ldg(&qv[hi[bs]]);
        sx += v.x; sy += v.y; sz += v.z;
        // advance winning list
#pragma unroll
        for (int s = 0; s < SEG; ++s) {
            if (s == bs) {
                long base = (((long)s * BB + b) * NN + qi) * KK;
                int  pp   = p[s];
                if (pp < KK) {
                    hd[s] = g_top_d[base + pp];
                    hi[s] = g_top_i[base + pp];
                } else {
                    hd[s] = __int_as_float(0x7f800000);
                }
                p[s] = pp + 1;
            }
        }
    }

    float4 myq = qv[qi];
    const float inv_k = 1.0f / (float)KK;
    float lx = sx * inv_k - myq.x;
    float ly = sy * inv_k - myq.y;
    float lz = sz * inv_k - myq.z;
    float contrib = fabsf(lx) + fabsf(ly) + fabsf(lz);

#pragma unroll
    for (int off = 16; off > 0; off >>= 1)
        contrib += __shfl_down_sync(0xffffffffu, contrib, off);
    if ((threadIdx.x & 31) == 0) wsum[threadIdx.x >> 5] = contrib;
    __syncthreads();
    if (threadIdx.x == 0) {
        float ssum = 0.0f;
#pragma unroll
        for (int w = 0; w < 256 / 32; ++w) ssum += wsum[w];
        atomicAdd(&g_acc, ssum);
    }
}

__global__ void finalize_kernel(float* __restrict__ out) {
    out[0] = g_acc * (1.0f / (float)(BB * NN * 3));
}

extern "C" void kernel_launch(void* const* d_in, const int* in_sizes, int n_in,
                              void* d_out, int out_size) {
    const float* p1 = (const float*)d_in[0];
    const float* p2 = (const float*)d_in[1];
    float* out = (float*)d_out;

    prep_kernel<<<(BB * NN + 255) / 256, 256>>>(p1, p2);
    dim3 grid(NN / TPB, BB, SEG);
    knn_seg_kernel<<<grid, TPB>>>();
    merge_loss_kernel<<<BB * NN / 256, 256>>>();
    finalize_kernel<<<1, 1>>>(out);
}

// round 3
// speedup vs baseline: 2.9960x; 2.9960x over previous
#include <cuda_runtime.h>
#include <cstdint>
#include <math_constants.h>

#define BB     2
#define NN     8192
#define KK     10
#define KS     11          // KK + 1 slot to absorb self
#define TPB    128
#define TILE   1024
#define SEG    2
#define SEGLEN (NN / SEG)  // 4096

// Scratch (no device allocation allowed)
__device__ float4 g_ptsA[BB * NN];             // {x, y, z, |p|^2}        (query form)
__device__ float4 g_ptsB[BB * NN];             // {-2x, -2y, -2z, |p|^2} (candidate form)
__device__ float4 g_q[BB * NN];                // {p1-p2, 0}
__device__ float  g_top_d[SEG * BB * NN * KS];
__device__ int    g_top_i[SEG * BB * NN * KS];
__device__ float  g_acc;

__global__ void prep_kernel(const float* __restrict__ p1,
                            const float* __restrict__ p2) {
    int i = blockIdx.x * blockDim.x + threadIdx.x;
    if (i == 0) g_acc = 0.0f;
    if (i < BB * NN) {
        float x = p1[3 * i + 0], y = p1[3 * i + 1], z = p1[3 * i + 2];
        float a = p2[3 * i + 0], b = p2[3 * i + 1], c = p2[3 * i + 2];
        float w = fmaf(z, z, fmaf(y, y, x * x));
        g_ptsA[i] = make_float4(x, y, z, w);
        g_ptsB[i] = make_float4(-2.0f * x, -2.0f * y, -2.0f * z, w);
        g_q[i]    = make_float4(x - a, y - b, z - c, 0.0f);
    }
}

// Branchless sorted insert into ascending 11-list. Inserting +inf is a no-op.
__device__ __forceinline__ void insert11(float v, int vi,
                                         float* __restrict__ dist,
                                         int* __restrict__ nn) {
    bool p[KS];
#pragma unroll
    for (int k = 0; k < KS; ++k) p[k] = v < dist[k];
#pragma unroll
    for (int k = KS - 1; k >= 1; --k) {
        dist[k] = p[k] ? (p[k - 1] ? dist[k - 1] : v) : dist[k];
        nn[k]   = p[k] ? (p[k - 1] ? nn[k - 1]  : vi) : nn[k];
    }
    dist[0] = p[0] ? v  : dist[0];
    nn[0]   = p[0] ? vi : nn[0];
}

// grid: (NN/TPB, BB, SEG). One thread per query; scans SEGLEN candidates.
__global__ __launch_bounds__(TPB) void knn_seg_kernel() {
    __shared__ float4 tile[TILE];

    const int b  = blockIdx.y;
    const int s  = blockIdx.z;
    const int qi = blockIdx.x * TPB + threadIdx.x;
    const int c0 = s * SEGLEN;
    const float4* __restrict__ cand = g_ptsB + b * NN;

    const float4 me = g_ptsA[b * NN + qi];

    float dist[KS];
    int   nn[KS];
#pragma unroll
    for (int k = 0; k < KS; ++k) {
        dist[k] = CUDART_INF_F;
        nn[k]   = -1;
    }

    for (int t = c0; t < c0 + SEGLEN; t += TILE) {
#pragma unroll
        for (int j = threadIdx.x; j < TILE; j += TPB)
            tile[j] = cand[t + j];
        __syncthreads();

        for (int j0 = 0; j0 < TILE; j0 += 4) {
            float d2v[4];
#pragma unroll
            for (int u = 0; u < 4; ++u) {
                float4 c = tile[j0 + u];
                d2v[u] = fmaf(c.x, me.x,
                         fmaf(c.y, me.y,
                         fmaf(c.z, me.z, me.w + c.w)));
            }
            float mn = fminf(fminf(d2v[0], d2v[1]), fminf(d2v[2], d2v[3]));
            if (__any_sync(0xffffffffu, mn < dist[KS - 1])) {
#pragma unroll
                for (int u = 0; u < 4; ++u) {
                    bool p = d2v[u] < dist[KS - 1];
                    if (__any_sync(0xffffffffu, p)) {
                        float v = p ? d2v[u] : CUDART_INF_F;
                        insert11(v, t + j0 + u, dist, nn);
                    }
                }
            }
        }
        __syncthreads();
    }

    long base = (((long)s * BB + b) * NN + qi) * KS;
#pragma unroll
    for (int k = 0; k < KS; ++k) {
        g_top_d[base + k] = dist[k];
        g_top_i[base + k] = nn[k];
    }
}

// One thread per query: 2-way merge of sorted 11-lists, skip self, take 10,
// then L1-loss contribution.  lap1-lap2 = mean_k q[nbr_k] - q_i, q = p1-p2.
__global__ __launch_bounds__(256) void merge_loss_kernel() {
    __shared__ float wsum[256 / 32];

    int q  = blockIdx.x * blockDim.x + threadIdx.x;
    int b  = q / NN;
    int qi = q - b * NN;

    long base0 = (((long)0 * BB + b) * NN + qi) * KS;
    long base1 = (((long)1 * BB + b) * NN + qi) * KS;

    float hd0 = g_top_d[base0], hd1 = g_top_d[base1];
    int   hi0 = g_top_i[base0], hi1 = g_top_i[base1];
    int   p0 = 1, p1 = 1;

    const float4* __restrict__ qv = g_q + b * NN;
    float sx = 0.0f, sy = 0.0f, sz = 0.0f;
    int cnt = 0;

#pragma unroll
    for (int step = 0; step < KS + 1; ++step) {
        if (cnt >= KK) break;
        int   idx;
        if (hd1 < hd0) {             // tie -> list 0 (lower indices) wins
            idx = hi1;
            hd1 = (p1 < KS) ? g_top_d[base1 + p1] : CUDART_INF_F;
            hi1 = (p1 < KS) ? g_top_i[base1 + p1] : -1;
            ++p1;
        } else {
            idx = hi0;
            hd0 = (p0 < KS) ? g_top_d[base0 + p0] : CUDART_INF_F;
            hi0 = (p0 < KS) ? g_top_i[base0 + p0] : -1;
            ++p0;
        }
        if (idx != qi && idx >= 0) {
            float4 v = __ldg(&qv[idx]);
            sx += v.x; sy += v.y; sz += v.z;
            ++cnt;
        }
    }

    float4 myq = qv[qi];
    const float inv_k = 1.0f / (float)KK;
    float lx = sx * inv_k - myq.x;
    float ly = sy * inv_k - myq.y;
    float lz = sz * inv_k - myq.z;
    float contrib = fabsf(lx) + fabsf(ly) + fabsf(lz);

#pragma unroll
    for (int off = 16; off > 0; off >>= 1)
        contrib += __shfl_down_sync(0xffffffffu, contrib, off);
    if ((threadIdx.x & 31) == 0) wsum[threadIdx.x >> 5] = contrib;
    __syncthreads();
    if (threadIdx.x == 0) {
        float ssum = 0.0f;
#pragma unroll
        for (int w = 0; w < 256 / 32; ++w) ssum += wsum[w];
        atomicAdd(&g_acc, ssum);
    }
}

__global__ void finalize_kernel(float* __restrict__ out) {
    out[0] = g_acc * (1.0f / (float)(BB * NN * 3));
}

extern "C" void kernel_launch(void* const* d_in, const int* in_sizes, int n_in,
                              void* d_out, int out_size) {
    const float* p1 = (const float*)d_in[0];
    const float* p2 = (const float*)d_in[1];
    float* out = (float*)d_out;

    prep_kernel<<<(BB * NN + 255) / 256, 256>>>(p1, p2);
    dim3 grid(NN / TPB, BB, SEG);
    knn_seg_kernel<<<grid, TPB>>>();
    merge_loss_kernel<<<BB * NN / 256, 256>>>();
    finalize_kernel<<<1, 1>>>(out);
}